// round 1
// baseline (speedup 1.0000x reference)
#include <cuda_runtime.h>
#include <math_constants.h>

#define SEQS   32
#define HEADS  32
#define KVH    8
#define GQA    4
#define HS     128
#define BS     16
#define MAXB   128
#define MAXLEN 2048
#define CHUNK  256
#define NCHUNKS 8
#define QSCALE 0.088388347648318447f   // 1/sqrt(128)

// Scratch partials (allocation-free rule: __device__ globals)
__device__ float g_part_m[SEQS][KVH][NCHUNKS][GQA];
__device__ float g_part_l[SEQS][KVH][NCHUNKS][GQA];
__device__ float g_part_acc[SEQS][KVH][NCHUNKS][GQA][HS];

__global__ void attn_chunk_kernel(const float* __restrict__ query,
                                  const float* __restrict__ kcache,
                                  const float* __restrict__ vcache,
                                  const int*   __restrict__ btab,
                                  const int*   __restrict__ seq_lens)
{
    const int c  = blockIdx.x;   // chunk
    const int kv = blockIdx.y;   // kv head
    const int s  = blockIdx.z;   // sequence

    const int len   = seq_lens[s];
    const int start = c * CHUNK;
    if (start >= len) return;
    const int end = min(start + CHUNK, len);

    const int tid  = threadIdx.x;
    const int w    = tid >> 5;
    const int lane = tid & 31;

    // Load the 4 grouped query heads: lane owns dims [lane*4, lane*4+4)
    float4 q[GQA];
#pragma unroll
    for (int g = 0; g < GQA; g++) {
        const float* qp = query + (size_t)s * (HEADS * HS) + (kv * GQA + g) * HS + lane * 4;
        q[g] = *reinterpret_cast<const float4*>(qp);
    }

    float m[GQA], l[GQA];
    float4 acc[GQA];
#pragma unroll
    for (int g = 0; g < GQA; g++) {
        m[g] = -CUDART_INF_F;
        l[g] = 0.0f;
        acc[g] = make_float4(0.f, 0.f, 0.f, 0.f);
    }

    const int* bt = btab + s * MAXB;

    // Software-pipelined token loop: warp w handles tokens start+w, start+w+4, ...
    int t = start + w;
    bool valid = (t < end);
    float4 k4 = make_float4(0.f,0.f,0.f,0.f);
    float4 v4 = make_float4(0.f,0.f,0.f,0.f);
    if (valid) {
        const int blk = bt[t >> 4];
        const int base = ((blk * BS + (t & 15)) * KVH + kv) * HS + lane * 4;
        k4 = *reinterpret_cast<const float4*>(kcache + base);
        v4 = *reinterpret_cast<const float4*>(vcache + base);
    }

    while (valid) {
        const int tn = t + 4;
        const bool vn = (tn < end);
        float4 k4n = k4, v4n = v4;
        if (vn) {
            const int blkn  = bt[tn >> 4];
            const int basen = ((blkn * BS + (tn & 15)) * KVH + kv) * HS + lane * 4;
            k4n = *reinterpret_cast<const float4*>(kcache + basen);
            v4n = *reinterpret_cast<const float4*>(vcache + basen);
        }

        // scores for 4 heads at token t
        float sc[GQA];
#pragma unroll
        for (int g = 0; g < GQA; g++) {
            float d = q[g].x * k4.x + q[g].y * k4.y + q[g].z * k4.z + q[g].w * k4.w;
            d += __shfl_xor_sync(0xffffffffu, d, 16);
            d += __shfl_xor_sync(0xffffffffu, d, 8);
            d += __shfl_xor_sync(0xffffffffu, d, 4);
            d += __shfl_xor_sync(0xffffffffu, d, 2);
            d += __shfl_xor_sync(0xffffffffu, d, 1);
            sc[g] = d * QSCALE;
        }

        // online softmax update
#pragma unroll
        for (int g = 0; g < GQA; g++) {
            const float mn   = fmaxf(m[g], sc[g]);
            const float corr = __expf(m[g] - mn);   // expf(-inf)=0 on first token
            const float p    = __expf(sc[g] - mn);
            l[g] = l[g] * corr + p;
            acc[g].x = acc[g].x * corr + p * v4.x;
            acc[g].y = acc[g].y * corr + p * v4.y;
            acc[g].z = acc[g].z * corr + p * v4.z;
            acc[g].w = acc[g].w * corr + p * v4.w;
            m[g] = mn;
        }

        t = tn; valid = vn; k4 = k4n; v4 = v4n;
    }

    // ---- cross-warp merge via shared memory ----
    __shared__ float sm_m[4][GQA];
    __shared__ float sm_l[4][GQA];
    __shared__ float sm_acc[4][GQA][HS];

    if (lane == 0) {
#pragma unroll
        for (int g = 0; g < GQA; g++) { sm_m[w][g] = m[g]; sm_l[w][g] = l[g]; }
    }
#pragma unroll
    for (int g = 0; g < GQA; g++) {
        sm_acc[w][g][lane * 4 + 0] = acc[g].x;
        sm_acc[w][g][lane * 4 + 1] = acc[g].y;
        sm_acc[w][g][lane * 4 + 2] = acc[g].z;
        sm_acc[w][g][lane * 4 + 3] = acc[g].w;
    }
    __syncthreads();

    // 128 threads: thread d merges dim d for all g
    const int d = tid;
#pragma unroll
    for (int g = 0; g < GQA; g++) {
        float M = sm_m[0][g];
        M = fmaxf(M, sm_m[1][g]);
        M = fmaxf(M, sm_m[2][g]);
        M = fmaxf(M, sm_m[3][g]);
        float L = 0.f, A = 0.f;
#pragma unroll
        for (int ww = 0; ww < 4; ww++) {
            const float f = __expf(sm_m[ww][g] - M);
            L += f * sm_l[ww][g];
            A += f * sm_acc[ww][g][d];
        }
        g_part_acc[s][kv][c][g][d] = A;
        if (tid == 0) {
            g_part_m[s][kv][c][g] = M;
            g_part_l[s][kv][c][g] = L;
        }
    }
}

__global__ void attn_reduce_kernel(const int* __restrict__ seq_lens,
                                   float* __restrict__ out)
{
    // one block per (s, kv, g)
    const int idx = blockIdx.x;
    const int g  = idx % GQA;
    const int kv = (idx / GQA) % KVH;
    const int s  = idx / (GQA * KVH);

    const int len = seq_lens[s];
    const int nch = (len + CHUNK - 1) / CHUNK;
    const int d = threadIdx.x;   // 128 threads

    float M = -CUDART_INF_F;
    for (int c = 0; c < nch; c++) M = fmaxf(M, g_part_m[s][kv][c][g]);

    float L = 0.f, A = 0.f;
    for (int c = 0; c < nch; c++) {
        const float f = __expf(g_part_m[s][kv][c][g] - M);
        L += f * g_part_l[s][kv][c][g];
        A += f * g_part_acc[s][kv][c][g][d];
    }

    out[(size_t)s * (HEADS * HS) + (kv * GQA + g) * HS + d] = A / L;
}

extern "C" void kernel_launch(void* const* d_in, const int* in_sizes, int n_in,
                              void* d_out, int out_size)
{
    const float* query  = (const float*)d_in[0];
    const float* kcache = (const float*)d_in[1];
    const float* vcache = (const float*)d_in[2];
    const int*   btab   = (const int*)d_in[3];
    const int*   slens  = (const int*)d_in[4];
    float* out = (float*)d_out;

    dim3 grid1(NCHUNKS, KVH, SEQS);
    attn_chunk_kernel<<<grid1, 128>>>(query, kcache, vcache, btab, slens);
    attn_reduce_kernel<<<SEQS * KVH * GQA, 128>>>(slens, out);
}

// round 2
// speedup vs baseline: 1.0286x; 1.0286x over previous
#include <cuda_runtime.h>
#include <math_constants.h>

#define SEQS    32
#define HEADS   32
#define KVH     8
#define GQA     4
#define HS      128
#define BS      16
#define MAXB    128
#define MAXLEN  2048
#define CHUNK   128
#define NCHUNKS 16
#define QSCALE  0.088388347648318447f      // 1/sqrt(128)
#define LOG2E   1.4426950408889634f

// Scratch partials (allocation-free rule: __device__ globals). m is in log2 domain.
__device__ float g_part_m[SEQS][KVH][NCHUNKS][GQA];
__device__ float g_part_l[SEQS][KVH][NCHUNKS][GQA];
__device__ float g_part_acc[SEQS][KVH][NCHUNKS][GQA][HS];

__device__ __forceinline__ float ex2(float x) {
    float y;
    asm("ex2.approx.f32 %0, %1;" : "=f"(y) : "f"(x));
    return y;   // ex2(-inf) = +0
}

__device__ __forceinline__ float warp_sum(float d) {
    d += __shfl_xor_sync(0xffffffffu, d, 16);
    d += __shfl_xor_sync(0xffffffffu, d, 8);
    d += __shfl_xor_sync(0xffffffffu, d, 4);
    d += __shfl_xor_sync(0xffffffffu, d, 2);
    d += __shfl_xor_sync(0xffffffffu, d, 1);
    return d;
}

__device__ __forceinline__ void load_kv(bool valid, const int* __restrict__ bt,
                                        int t, int kv, int lane,
                                        const float* __restrict__ kc,
                                        const float* __restrict__ vc,
                                        float4& k4, float4& v4)
{
    if (valid) {
        const int blk  = __ldg(bt + (t >> 4));
        const size_t base = (((size_t)blk * BS + (t & 15)) * KVH + kv) * HS + lane * 4;
        k4 = *reinterpret_cast<const float4*>(kc + base);
        v4 = *reinterpret_cast<const float4*>(vc + base);
    } else {
        k4 = make_float4(0.f, 0.f, 0.f, 0.f);
        v4 = make_float4(0.f, 0.f, 0.f, 0.f);
    }
}

__global__ void attn_chunk_kernel(const float* __restrict__ query,
                                  const float* __restrict__ kcache,
                                  const float* __restrict__ vcache,
                                  const int*   __restrict__ btab,
                                  const int*   __restrict__ seq_lens)
{
    const int c  = blockIdx.x;   // chunk
    const int kv = blockIdx.y;   // kv head
    const int s  = blockIdx.z;   // sequence

    const int len   = seq_lens[s];
    const int start = c * CHUNK;
    if (start >= len) return;
    const int end = min(start + CHUNK, len);

    const int tid  = threadIdx.x;
    const int w    = tid >> 5;
    const int lane = tid & 31;

    // Q for 4 grouped heads, pre-scaled into log2 domain. Lane owns dims [lane*4, lane*4+4).
    float4 q[GQA];
#pragma unroll
    for (int g = 0; g < GQA; g++) {
        const float* qp = query + (size_t)s * (HEADS * HS) + (kv * GQA + g) * HS + lane * 4;
        float4 t4 = *reinterpret_cast<const float4*>(qp);
        const float sc = QSCALE * LOG2E;
        q[g] = make_float4(t4.x * sc, t4.y * sc, t4.z * sc, t4.w * sc);
    }

    float m[GQA], l[GQA];
    float4 acc[GQA];
#pragma unroll
    for (int g = 0; g < GQA; g++) {
        m[g] = -CUDART_INF_F;
        l[g] = 0.0f;
        acc[g] = make_float4(0.f, 0.f, 0.f, 0.f);
    }

    const int* bt = btab + s * MAXB;

    // Warp w handles contiguous tokens [start + w*32, min(start + (w+1)*32, end)),
    // two tokens per iteration, depth-2 software pipeline (4 loads in flight).
    const int t0   = start + w * 32;
    const int tend = min(t0 + 32, end);

    if (t0 < tend) {
        float4 ka, va, kb, vb;
        load_kv(true,          bt, t0,     kv, lane, kcache, vcache, ka, va);
        load_kv(t0 + 1 < tend, bt, t0 + 1, kv, lane, kcache, vcache, kb, vb);

        for (int t = t0; t < tend; t += 2) {
            // prefetch next pair
            float4 kna, vna, knb, vnb;
            const int tn = t + 2;
            load_kv(tn     < tend, bt, tn,     kv, lane, kcache, vcache, kna, vna);
            load_kv(tn + 1 < tend, bt, tn + 1, kv, lane, kcache, vcache, knb, vnb);

            const bool vB = (t + 1 < tend);

            // scores (log2 domain) for the pair, all 4 heads
            float sa[GQA], sb[GQA];
#pragma unroll
            for (int g = 0; g < GQA; g++) {
                float da = q[g].x * ka.x + q[g].y * ka.y + q[g].z * ka.z + q[g].w * ka.w;
                float db = q[g].x * kb.x + q[g].y * kb.y + q[g].z * kb.z + q[g].w * kb.w;
                sa[g] = warp_sum(da);
                sb[g] = vB ? warp_sum(db) : -CUDART_INF_F;
            }

            // batched online-softmax update (one corr per pair)
#pragma unroll
            for (int g = 0; g < GQA; g++) {
                const float mx   = fmaxf(sa[g], sb[g]);
                const float mn   = fmaxf(m[g], mx);
                const float corr = ex2(m[g] - mn);
                const float pa   = ex2(sa[g] - mn);
                const float pb   = ex2(sb[g] - mn);
                m[g] = mn;
                l[g] = l[g] * corr + pa + pb;
                acc[g].x = acc[g].x * corr + pa * va.x + pb * vb.x;
                acc[g].y = acc[g].y * corr + pa * va.y + pb * vb.y;
                acc[g].z = acc[g].z * corr + pa * va.z + pb * vb.z;
                acc[g].w = acc[g].w * corr + pa * va.w + pb * vb.w;
            }

            ka = kna; va = vna; kb = knb; vb = vnb;
        }
    }

    // ---- cross-warp merge via shared memory ----
    __shared__ float sm_m[4][GQA];
    __shared__ float sm_l[4][GQA];
    __shared__ float sm_acc[4][GQA][HS];

    if (lane == 0) {
#pragma unroll
        for (int g = 0; g < GQA; g++) { sm_m[w][g] = m[g]; sm_l[w][g] = l[g]; }
    }
#pragma unroll
    for (int g = 0; g < GQA; g++) {
        sm_acc[w][g][lane * 4 + 0] = acc[g].x;
        sm_acc[w][g][lane * 4 + 1] = acc[g].y;
        sm_acc[w][g][lane * 4 + 2] = acc[g].z;
        sm_acc[w][g][lane * 4 + 3] = acc[g].w;
    }
    __syncthreads();

    const int d = tid;   // 128 threads, one dim each
#pragma unroll
    for (int g = 0; g < GQA; g++) {
        float M = sm_m[0][g];
        M = fmaxf(M, sm_m[1][g]);
        M = fmaxf(M, sm_m[2][g]);
        M = fmaxf(M, sm_m[3][g]);
        float L = 0.f, A = 0.f;
#pragma unroll
        for (int ww = 0; ww < 4; ww++) {
            const float f = ex2(sm_m[ww][g] - M);
            L += f * sm_l[ww][g];
            A += f * sm_acc[ww][g][d];
        }
        g_part_acc[s][kv][c][g][d] = A;
        if (tid == 0) {
            g_part_m[s][kv][c][g] = M;
            g_part_l[s][kv][c][g] = L;
        }
    }
}

__global__ void attn_reduce_kernel(const int* __restrict__ seq_lens,
                                   float* __restrict__ out)
{
    // one block per (s, kv, g)
    const int idx = blockIdx.x;
    const int g  = idx % GQA;
    const int kv = (idx / GQA) % KVH;
    const int s  = idx / (GQA * KVH);

    const int len = seq_lens[s];
    const int nch = (len + CHUNK - 1) / CHUNK;
    const int d = threadIdx.x;   // 128 threads

    float M = -CUDART_INF_F;
    for (int c = 0; c < nch; c++) M = fmaxf(M, g_part_m[s][kv][c][g]);

    float L = 0.f, A = 0.f;
    for (int c = 0; c < nch; c++) {
        const float f = ex2(g_part_m[s][kv][c][g] - M);
        L += f * g_part_l[s][kv][c][g];
        A += f * g_part_acc[s][kv][c][g][d];
    }

    out[(size_t)s * (HEADS * HS) + (kv * GQA + g) * HS + d] = A / L;
}

extern "C" void kernel_launch(void* const* d_in, const int* in_sizes, int n_in,
                              void* d_out, int out_size)
{
    const float* query  = (const float*)d_in[0];
    const float* kcache = (const float*)d_in[1];
    const float* vcache = (const float*)d_in[2];
    const int*   btab   = (const int*)d_in[3];
    const int*   slens  = (const int*)d_in[4];
    float* out = (float*)d_out;

    dim3 grid1(NCHUNKS, KVH, SEQS);
    attn_chunk_kernel<<<grid1, 128>>>(query, kcache, vcache, btab, slens);
    attn_reduce_kernel<<<SEQS * KVH * GQA, 128>>>(slens, out);
}

// round 5
// speedup vs baseline: 1.1926x; 1.1594x over previous
#include <cuda_runtime.h>
#include <math_constants.h>
#include <cstdint>

#define SEQS    32
#define HEADS   32
#define KVH     8
#define GQA     4
#define HS      128
#define BS      16
#define MAXB    128
#define CHUNK   128
#define NCHUNKS 16
#define TILE    16
#define QSCALE  0.088388347648318447f      // 1/sqrt(128)
#define LOG2E   1.4426950408889634f
#define RSTRIDE 34                         // float4 per padded row (128 floats + 2x16B pad)

// Scratch partials (allocation-free rule). m is in log2 domain.
__device__ float g_part_m[SEQS][KVH][NCHUNKS][GQA];
__device__ float g_part_l[SEQS][KVH][NCHUNKS][GQA];
__device__ float g_part_acc[SEQS][KVH][NCHUNKS][GQA][HS];

__device__ __forceinline__ float ex2(float x) {
    float y; asm("ex2.approx.f32 %0, %1;" : "=f"(y) : "f"(x)); return y;  // ex2(-inf)=+0
}
__device__ __forceinline__ void cpa16(unsigned saddr, const void* gaddr) {
    asm volatile("cp.async.cg.shared.global [%0], [%1], 16;" :: "r"(saddr), "l"(gaddr));
}
__device__ __forceinline__ void cp_commit() { asm volatile("cp.async.commit_group;"); }
__device__ __forceinline__ void cp_wait1()  { asm volatile("cp.async.wait_group 1;"); }

__global__ __launch_bounds__(128) void attn_chunk_kernel(
    const float* __restrict__ query,
    const float* __restrict__ kcache,
    const float* __restrict__ vcache,
    const int*   __restrict__ btab,
    const int*   __restrict__ seq_lens)
{
    const int c  = blockIdx.x;   // chunk
    const int kv = blockIdx.y;   // kv head
    const int s  = blockIdx.z;   // sequence

    const int len   = seq_lens[s];
    const int start = c * CHUNK;
    if (start >= len) return;
    const int nt     = min(CHUNK, len - start);
    const int ntiles = (nt + TILE - 1) / TILE;

    __shared__ float4 sK[2][TILE * RSTRIDE];   // 2 x 8704 B
    __shared__ float4 sV[2][TILE * RSTRIDE];   // 2 x 8704 B
    __shared__ float4 sQ[GQA * RSTRIDE];       // padded like K rows
    __shared__ float  sP[TILE * GQA];
    __shared__ float  sWmax[4][GQA];
    __shared__ float  sLsum[4][GQA];

    const int tid  = threadIdx.x;
    const int w    = tid >> 5;
    const int lane = tid & 31;

    // Score-phase roles: lane = h*16 + t*4 + g  (h: dim half, t: token-in-warp, g: head)
    const int g_s = lane & 3;
    const int t_s = (lane >> 2) & 3;
    const int h   = lane >> 4;
    // PV-phase roles: lane = g*8 + dp  (g: head, dp: dim quad within warp's 32 dims)
    const int g_p  = lane >> 3;
    const int dp   = lane & 7;
    const int jcol = w * 8 + dp;                 // float4 column 0..31 (dims jcol*4..+3)
    const int vcol = jcol + (jcol >= 16 ? 1 : 0);

    // Load + pre-scale Q (one float4 per thread): sQ[g][padded]
    {
        const int g = tid >> 5, j = tid & 31;
        const float4 qv = *reinterpret_cast<const float4*>(
            query + (size_t)s * (HEADS * HS) + (kv * GQA + g) * HS + j * 4);
        const float scl = QSCALE * LOG2E;
        sQ[g * RSTRIDE + j + (j >= 16 ? 1 : 0)] =
            make_float4(qv.x * scl, qv.y * scl, qv.z * scl, qv.w * scl);
    }

    const int* bt = btab + s * MAXB;
    const int  blk0 = start >> 4;   // first page index of this chunk (CHUNK % 16 == 0)

    // Per-thread staging geometry (same for every tile): thread covers 4 float4 slots.
    const unsigned skbase = (unsigned)__cvta_generic_to_shared(&sK[0][0]);
    const unsigned svbase = (unsigned)__cvta_generic_to_shared(&sV[0][0]);
    const unsigned bufstride = (unsigned)(TILE * RSTRIDE * sizeof(float4));

    // cp.async stage of one 16-token page (K and V) into buffer `buf`
    auto load_tile = [&](int buf, int ti) {
        const int blk = __ldg(bt + blk0 + ti);
        const size_t pbase = (size_t)blk * (BS * KVH * HS) + (size_t)kv * HS;
        const unsigned kdst = skbase + buf * bufstride;
        const unsigned vdst = svbase + buf * bufstride;
#pragma unroll
        for (int i = 0; i < 4; i++) {
            const int idx = tid + 128 * i;       // 0..511 float4 slots
            const int r = idx >> 5, j = idx & 31;
            const size_t goff = pbase + (size_t)r * (KVH * HS) + j * 4;
            const unsigned soff = (unsigned)((r * RSTRIDE + j + (j >= 16 ? 1 : 0)) * sizeof(float4));
            cpa16(kdst + soff, kcache + goff);
            cpa16(vdst + soff, vcache + goff);
        }
    };

    load_tile(0, 0);
    cp_commit();
    if (ntiles > 1) load_tile(1, 1);
    cp_commit();

    float  m_s = -CUDART_INF_F, m_p = -CUDART_INF_F, l_s = 0.f;
    float4 acc = make_float4(0.f, 0.f, 0.f, 0.f);

    const int kb = (w * 4 + t_s) * RSTRIDE + h * 17;   // K row base (float4 units)
    const int qb = g_s * RSTRIDE + h * 17;

    for (int i = 0; i < ntiles; i++) {
        const int b = i & 1;
        cp_wait1();
        __syncthreads();                                  // tile i staged & visible

        // ---- QK scores: lane does a 64-dim partial dot for (token, head) ----
        const float4* Kf = sK[b];
        float d0 = 0.f, d1 = 0.f;
#pragma unroll
        for (int dd = 0; dd < 16; dd += 2) {
            const float4 k0 = Kf[kb + dd],     q0 = sQ[qb + dd];
            const float4 k1 = Kf[kb + dd + 1], q1 = sQ[qb + dd + 1];
            d0 = fmaf(k0.x, q0.x, d0); d0 = fmaf(k0.y, q0.y, d0);
            d0 = fmaf(k0.z, q0.z, d0); d0 = fmaf(k0.w, q0.w, d0);
            d1 = fmaf(k1.x, q1.x, d1); d1 = fmaf(k1.y, q1.y, d1);
            d1 = fmaf(k1.z, q1.z, d1); d1 = fmaf(k1.w, q1.w, d1);
        }
        float dot = d0 + d1;
        dot += __shfl_xor_sync(0xffffffffu, dot, 16);     // combine dim halves

        const int tok = start + i * TILE + (w * 4 + t_s);
        const float sc = (tok < len) ? dot : -CUDART_INF_F;

        // warp-local per-head max over its 4 tokens
        float wm = sc;
        wm = fmaxf(wm, __shfl_xor_sync(0xffffffffu, wm, 8));
        wm = fmaxf(wm, __shfl_xor_sync(0xffffffffu, wm, 4));
        if (lane < 4) sWmax[w][lane] = wm;
        __syncthreads();

        // tile max per head (shared across warps), for both lane roles
        const float tm_s = fmaxf(fmaxf(sWmax[0][g_s], sWmax[1][g_s]),
                                 fmaxf(sWmax[2][g_s], sWmax[3][g_s]));
        const float tm_p = fmaxf(fmaxf(sWmax[0][g_p], sWmax[1][g_p]),
                                 fmaxf(sWmax[2][g_p], sWmax[3][g_p]));

        const float mns = fmaxf(m_s, tm_s);
        const float p   = ex2(sc - mns);
        l_s = l_s * ex2(m_s - mns) + (h == 0 ? p : 0.f);
        m_s = mns;
        if (h == 0) sP[(w * 4 + t_s) * 4 + g_s] = p;

        const float mnp  = fmaxf(m_p, tm_p);
        const float corr = ex2(m_p - mnp);
        m_p = mnp;
        __syncthreads();                                  // sP visible

        // ---- PV: lane owns (head g_p, 4 dims), loops 16 tokens ----
        const float4* Vf = sV[b];
        acc.x *= corr; acc.y *= corr; acc.z *= corr; acc.w *= corr;
#pragma unroll
        for (int t = 0; t < TILE; t++) {
            const float4 vv = Vf[t * RSTRIDE + vcol];
            const float  pp = sP[t * 4 + g_p];
            acc.x = fmaf(pp, vv.x, acc.x);
            acc.y = fmaf(pp, vv.y, acc.y);
            acc.z = fmaf(pp, vv.z, acc.z);
            acc.w = fmaf(pp, vv.w, acc.w);
        }
        __syncthreads();                                  // done with buffer b & sP

        if (i + 2 < ntiles) load_tile(b, i + 2);
        cp_commit();
    }

    // ---- epilogue: reduce l across lanes/warps; write partials ----
    float L = l_s;
    L += __shfl_xor_sync(0xffffffffu, L, 16);
    L += __shfl_xor_sync(0xffffffffu, L, 8);
    L += __shfl_xor_sync(0xffffffffu, L, 4);
    if (lane < 4) sLsum[w][lane] = L;
    __syncthreads();
    if (w == 0 && lane < 4) {
        g_part_m[s][kv][c][lane] = m_s;   // lane<4 => g_s == lane; m_s identical across warps
        g_part_l[s][kv][c][lane] =
            sLsum[0][lane] + sLsum[1][lane] + sLsum[2][lane] + sLsum[3][lane];
    }
    *reinterpret_cast<float4*>(&g_part_acc[s][kv][c][g_p][jcol * 4]) = acc;
}

__global__ void attn_reduce_kernel(const int* __restrict__ seq_lens,
                                   float* __restrict__ out)
{
    // one block per (s, kv, g)
    const int idx = blockIdx.x;
    const int g  = idx % GQA;
    const int kv = (idx / GQA) % KVH;
    const int s  = idx / (GQA * KVH);

    const int len = seq_lens[s];
    const int nch = (len + CHUNK - 1) / CHUNK;
    const int d = threadIdx.x;   // 128 threads

    float M = -CUDART_INF_F;
#pragma unroll 4
    for (int c = 0; c < nch; c++) M = fmaxf(M, g_part_m[s][kv][c][g]);

    float L = 0.f, A = 0.f;
#pragma unroll 4
    for (int c = 0; c < nch; c++) {
        const float f = ex2(g_part_m[s][kv][c][g] - M);
        L += f * g_part_l[s][kv][c][g];
        A += f * g_part_acc[s][kv][c][g][d];
    }

    out[(size_t)s * (HEADS * HS) + (kv * GQA + g) * HS + d] = A / L;
}

extern "C" void kernel_launch(void* const* d_in, const int* in_sizes, int n_in,
                              void* d_out, int out_size)
{
    const float* query  = (const float*)d_in[0];
    const float* kcache = (const float*)d_in[1];
    const float* vcache = (const float*)d_in[2];
    const int*   btab   = (const int*)d_in[3];
    const int*   slens  = (const int*)d_in[4];
    float* out = (float*)d_out;

    dim3 grid1(NCHUNKS, KVH, SEQS);
    attn_chunk_kernel<<<grid1, 128>>>(query, kcache, vcache, btab, slens);
    attn_reduce_kernel<<<SEQS * KVH * GQA, 128>>>(slens, out);
}